// round 9
// baseline (speedup 1.0000x reference)
#include <cuda_runtime.h>
#include <cuda_bf16.h>
#include <stdint.h>

// LSTM_3444563771996 : I=28, H=64, T=128, B=4096, OUT=10
// Warp-specialized persistent LSTM (8 GEMM + 8 ACT warps, 2 batch groups).
// K-split: gates(t) = xw(t) [bias + W_ih*x(t), computed one step early,
// off the h-dependency path] + W_hh*h(t-1) [K=64 critical GEMM].
// bf16 hi/lo split mma.sync, fp32 accum: D += Whi*Ahi + Whi*Alo + Wlo*Ahi.

#define TI   128
#define II   28
#define HH   64
#define GG   256
#define KK   92
#define BB   4096
#define OUTD 10
#define MB   32
#define NTHR 512
#define HST  72      // h / W_hh tile row stride (elems): 144B, ldmatrix conflict-free
#define XST  40      // x / W_ih tile row stride (elems): 80B, conflict-free
#define GST  33      // Gs float stride

// ---- SMEM byte offsets ----
#define SM_WHH_HI 0                              // 256*72*2 = 36864
#define SM_WHH_LO (SM_WHH_HI + GG * HST * 2)     //  36864
#define SM_WIH_HI (SM_WHH_LO + GG * HST * 2)     //  73728 (256*40*2 = 20480)
#define SM_WIH_LO (SM_WIH_HI + GG * XST * 2)     //  94208
#define SM_H_HI   (SM_WIH_LO + GG * XST * 2)     // 114688 (32*72*2 = 4608)
#define SM_H_LO   (SM_H_HI + MB * HST * 2)       // 119296
#define SM_X      (SM_H_LO + MB * HST * 2)       // 123904: [2 buf][hi,lo][32][40]
#define XBUF      5120                           // per-buf bytes (hi+lo planes)
#define XPLANE    2560
#define SM_XW     (SM_X + 2 * XBUF)              // 134144: [2 g][8 warp][32 lane][20 f]
#define XWG       20480
#define SM_GS     (SM_XW + 2 * XWG)              // 175104 (256*33*4 = 33792)
#define SM_HS     (SM_GS + GG * GST * 4)         // 208896 (32*64*4 = 8192)
#define SMEM_BYTES (SM_HS + MB * HH * 4)         // 217088

typedef unsigned long long u64;

#define LDSM4(r, addr)                                                        \
    asm volatile("ldmatrix.sync.aligned.m8n8.x4.shared.b16 {%0,%1,%2,%3}, [%4];" \
                 : "=r"((r)[0]), "=r"((r)[1]), "=r"((r)[2]), "=r"((r)[3])     \
                 : "r"(addr))

#define MMA16816(d, a, b0_, b1_)                                              \
    asm volatile("mma.sync.aligned.m16n8k16.row.col.f32.bf16.bf16.f32 "       \
                 "{%0,%1,%2,%3}, {%4,%5,%6,%7}, {%8,%9}, {%0,%1,%2,%3};"      \
                 : "+f"((d)[0]), "+f"((d)[1]), "+f"((d)[2]), "+f"((d)[3])     \
                 : "r"((a)[0]), "r"((a)[1]), "r"((a)[2]), "r"((a)[3]),        \
                   "r"(b0_), "r"(b1_))

#define BSYNC(id) asm volatile("bar.sync %0, %1;"   :: "r"(id), "r"(NTHR) : "memory")
#define BARR(id)  asm volatile("bar.arrive %0, %1;" :: "r"(id), "r"(NTHR) : "memory")

static __device__ __forceinline__ uint32_t smem_u32(const void* p) {
    uint32_t a;
    asm("{ .reg .u64 t; cvta.to.shared.u64 t, %1; cvt.u32.u64 %0, t; }" : "=r"(a) : "l"(p));
    return a;
}
static __device__ __forceinline__ void split_bf16(float v, uint16_t& hi, uint16_t& lo) {
    __nv_bfloat16 h = __float2bfloat16_rn(v);
    __nv_bfloat16 l = __float2bfloat16_rn(v - __bfloat162float(h));
    hi = __bfloat16_as_ushort(h);
    lo = __bfloat16_as_ushort(l);
}
static __device__ __forceinline__ float sigm_(float v) {
    return __fdividef(1.0f, 1.0f + __expf(-v));
}
static __device__ __forceinline__ float tanh_(float v) {
    float e = __expf(-2.0f * v);
    return __fdividef(2.0f, 1.0f + e) - 1.0f;
}
static __device__ __forceinline__ void pack_x(const float4& xv, u64& ph, u64& pl) {
    uint16_t h0,l0,h1,l1,h2,l2,h3,l3;
    split_bf16(xv.x, h0, l0); split_bf16(xv.y, h1, l1);
    split_bf16(xv.z, h2, l2); split_bf16(xv.w, h3, l3);
    ph = (u64)h0 | ((u64)h1 << 16) | ((u64)h2 << 32) | ((u64)h3 << 48);
    pl = (u64)l0 | ((u64)l1 << 16) | ((u64)l2 << 32) | ((u64)l3 << 48);
}

__global__ __launch_bounds__(NTHR, 1)
void lstm_kernel(const float* __restrict__ x,
                 const float* __restrict__ W_ih, const float* __restrict__ W_hh,
                 const float* __restrict__ b_ih, const float* __restrict__ b_hh,
                 const float* __restrict__ W_out, const float* __restrict__ b_out,
                 float* __restrict__ out)
{
    extern __shared__ char smem[];
    const uint32_t sb = smem_u32(smem);
    float* Gs = (float*)(smem + SM_GS);
    float* Hs = (float*)(smem + SM_HS);

    const int tid  = threadIdx.x;
    const int lane = tid & 31;
    const int warp = tid >> 5;
    const int b0   = blockIdx.x * MB;

    // ---- zero all staging (padding + h0 = 0) ----
    for (int i = tid; i < SM_GS / 4; i += NTHR) ((uint32_t*)smem)[i] = 0u;
    __syncthreads();

    // ---- stage W_hh hi/lo [gate][k0..63] ----
    for (int idx = tid; idx < GG * HH; idx += NTHR) {
        int g = idx >> 6, k = idx & 63;
        uint16_t hi, lo; split_bf16(W_hh[g * HH + k], hi, lo);
        *(uint16_t*)(smem + SM_WHH_HI + (g * HST + k) * 2) = hi;
        *(uint16_t*)(smem + SM_WHH_LO + (g * HST + k) * 2) = lo;
    }
    // ---- stage W_ih hi/lo [gate][k0..27] ----
    for (int idx = tid; idx < GG * II; idx += NTHR) {
        int g = idx / II, k = idx - g * II;
        uint16_t hi, lo; split_bf16(W_ih[g * II + k], hi, lo);
        *(uint16_t*)(smem + SM_WIH_HI + (g * XST + k) * 2) = hi;
        *(uint16_t*)(smem + SM_WIH_LO + (g * XST + k) * 2) = lo;
    }
    // ---- stage x(0) -> buf0, x(1) -> buf1 ----
    for (int idx = tid; idx < 2 * MB * 7; idx += NTHR) {
        int ts = idx / (MB * 7), rem = idx % (MB * 7);
        int row = rem / 7, seg = rem % 7;
        const float4 xv = *reinterpret_cast<const float4*>(
            x + ((size_t)(b0 + row) * TI + ts) * II + seg * 4);
        u64 ph, pl; pack_x(xv, ph, pl);
        *(u64*)(smem + SM_X + ts * XBUF + (row * XST + seg * 4) * 2)          = ph;
        *(u64*)(smem + SM_X + ts * XBUF + XPLANE + (row * XST + seg * 4) * 2) = pl;
    }
    __syncthreads();

    if (warp < 8) {
        // ================= GEMM role (warps 0-7) =================
        const int l7 = lane & 7, lg = lane >> 3;
        const int wrow = l7 + ((lg & 1) << 3);
        const int wkh  = lg >> 1;
        const int arow0 = l7 + ((lg >> 1) << 3);
        const int akh   = lg & 1;

        const uint32_t whhH = sb + SM_WHH_HI + (((warp * 32 + wrow) * HST) + wkh * 8) * 2;
        const uint32_t whhL = sb + SM_WHH_LO + (((warp * 32 + wrow) * HST) + wkh * 8) * 2;
        const uint32_t wihH = sb + SM_WIH_HI + (((warp * 32 + wrow) * XST) + wkh * 8) * 2;
        const uint32_t wihL = sb + SM_WIH_LO + (((warp * 32 + wrow) * XST) + wkh * 8) * 2;
        uint32_t hHg[2], hLg[2], xofg[2];
        float4* xwp[2];
#pragma unroll
        for (int g = 0; g < 2; ++g) {
            hHg[g] = sb + SM_H_HI + (((g * 16 + arow0) * HST) + akh * 8) * 2;
            hLg[g] = sb + SM_H_LO + (((g * 16 + arow0) * HST) + akh * 8) * 2;
            xofg[g] = ((g * 16 + arow0) * XST + akh * 8) * 2;
            xwp[g] = (float4*)(smem + SM_XW + g * XWG + warp * 2560 + lane * 80);
        }

        // resident W_hh-hi fragments (32 regs)
        uint32_t whhR[4][2][4];
#pragma unroll
        for (int kc = 0; kc < 4; ++kc)
#pragma unroll
            for (int mt = 0; mt < 2; ++mt)
                LDSM4(whhR[kc][mt], whhH + mt * 16 * HST * 2 + kc * 32);

        const int grow = lane >> 2;
        const int bcol = (lane & 3) * 2;
        float biasA[2], biasB[2];
#pragma unroll
        for (int mt = 0; mt < 2; ++mt) {
            int g1 = warp * 32 + mt * 16 + grow;
            biasA[mt] = b_ih[g1]     + b_hh[g1];
            biasB[mt] = b_ih[g1 + 8] + b_hh[g1 + 8];
        }

        // xw(t) = bias + W_ih * x(t) for group g from x buffer `buf`
        auto xw_compute = [&](int g, int buf) {
            float a[2][2][4];
#pragma unroll
            for (int mt = 0; mt < 2; ++mt)
#pragma unroll
                for (int j = 0; j < 2; ++j) {
                    a[mt][j][0] = biasA[mt]; a[mt][j][1] = biasA[mt];
                    a[mt][j][2] = biasB[mt]; a[mt][j][3] = biasB[mt];
                }
            const uint32_t xh = sb + SM_X + buf * XBUF + xofg[g];
            const uint32_t xl = xh + XPLANE;
#pragma unroll
            for (int kc = 0; kc < 2; ++kc) {
                uint32_t wh0[4], wh1[4], wl0[4], wl1[4], bh[4], bl[4];
                LDSM4(wh0, wihH + kc * 32);
                LDSM4(wh1, wihH + 16 * XST * 2 + kc * 32);
                LDSM4(wl0, wihL + kc * 32);
                LDSM4(wl1, wihL + 16 * XST * 2 + kc * 32);
                LDSM4(bh, xh + kc * 32);
                LDSM4(bl, xl + kc * 32);
                MMA16816(a[0][0], wh0, bh[0], bh[1]);
                MMA16816(a[0][1], wh0, bh[2], bh[3]);
                MMA16816(a[0][0], wh0, bl[0], bl[1]);
                MMA16816(a[0][1], wh0, bl[2], bl[3]);
                MMA16816(a[0][0], wl0, bh[0], bh[1]);
                MMA16816(a[0][1], wl0, bh[2], bh[3]);
                MMA16816(a[1][0], wh1, bh[0], bh[1]);
                MMA16816(a[1][1], wh1, bh[2], bh[3]);
                MMA16816(a[1][0], wh1, bl[0], bl[1]);
                MMA16816(a[1][1], wh1, bl[2], bl[3]);
                MMA16816(a[1][0], wl1, bh[0], bh[1]);
                MMA16816(a[1][1], wl1, bh[2], bh[3]);
            }
#pragma unroll
            for (int mt = 0; mt < 2; ++mt)
#pragma unroll
                for (int j = 0; j < 2; ++j)
                    xwp[g][mt * 2 + j] = make_float4(a[mt][j][0], a[mt][j][1],
                                                     a[mt][j][2], a[mt][j][3]);
        };

        // prologue: xw(0) for both groups (x(0) in buf0)
        xw_compute(0, 0);
        xw_compute(1, 0);

        for (int t = 0; t < TI; ++t) {
#pragma unroll
            for (int g = 0; g < 2; ++g) {
                BSYNC(1 + g);              // h(t-1,g) ready
                float acc[2][2][4];
#pragma unroll
                for (int mt = 0; mt < 2; ++mt)
#pragma unroll
                    for (int j = 0; j < 2; ++j) {
                        float4 q = xwp[g][mt * 2 + j];
                        acc[mt][j][0] = q.x; acc[mt][j][1] = q.y;
                        acc[mt][j][2] = q.z; acc[mt][j][3] = q.w;
                    }
#pragma unroll
                for (int kc = 0; kc < 4; ++kc) {
                    uint32_t wl0[4], wl1[4], bh[4], bl[4];
                    LDSM4(wl0, whhL + kc * 32);
                    LDSM4(wl1, whhL + 16 * HST * 2 + kc * 32);
                    LDSM4(bh, hHg[g] + kc * 32);
                    LDSM4(bl, hLg[g] + kc * 32);
                    MMA16816(acc[0][0], whhR[kc][0], bh[0], bh[1]);
                    MMA16816(acc[0][1], whhR[kc][0], bh[2], bh[3]);
                    MMA16816(acc[0][0], whhR[kc][0], bl[0], bl[1]);
                    MMA16816(acc[0][1], whhR[kc][0], bl[2], bl[3]);
                    MMA16816(acc[0][0], wl0, bh[0], bh[1]);
                    MMA16816(acc[0][1], wl0, bh[2], bh[3]);
                    MMA16816(acc[1][0], whhR[kc][1], bh[0], bh[1]);
                    MMA16816(acc[1][1], whhR[kc][1], bh[2], bh[3]);
                    MMA16816(acc[1][0], whhR[kc][1], bl[0], bl[1]);
                    MMA16816(acc[1][1], whhR[kc][1], bl[2], bl[3]);
                    MMA16816(acc[1][0], wl1, bh[0], bh[1]);
                    MMA16816(acc[1][1], wl1, bh[2], bh[3]);
                }
#pragma unroll
                for (int mt = 0; mt < 2; ++mt)
#pragma unroll
                    for (int j = 0; j < 2; ++j) {
                        const int g1 = warp * 32 + mt * 16 + grow;
                        const int bb = g * 16 + j * 8 + bcol;
                        Gs[g1 * GST + bb]           = acc[mt][j][0];
                        Gs[g1 * GST + bb + 1]       = acc[mt][j][1];
                        Gs[(g1 + 8) * GST + bb]     = acc[mt][j][2];
                        Gs[(g1 + 8) * GST + bb + 1] = acc[mt][j][3];
                    }
                BARR(3 + g);               // gates(t,g) ready
                if (t + 1 < TI) xw_compute(g, (t + 1) & 1);  // off h-path
            }
        }
    } else {
        // ================= ACT role (warps 8-15) =================
        const int gtid = tid - 256;
        const int u  = gtid & 63;
        const int rb = (gtid >> 6) * 4;
        const bool stager = gtid < 16 * 7;
        const int sgrow = gtid / 7, seg = gtid % 7;
        float cst[2][4];
#pragma unroll
        for (int g = 0; g < 2; ++g)
#pragma unroll
            for (int r = 0; r < 4; ++r) cst[g][r] = 0.0f;

        // prefetch x(2) for both groups into registers
        float4 xreg[2];
        if (stager) {
#pragma unroll
            for (int g = 0; g < 2; ++g)
                xreg[g] = *reinterpret_cast<const float4*>(
                    x + ((size_t)(b0 + g * 16 + sgrow) * TI + 2) * II + seg * 4);
        }
        BARR(1);
        BARR(2);

        for (int t = 0; t < TI; ++t) {
#pragma unroll
            for (int g = 0; g < 2; ++g) {
                BSYNC(3 + g);              // gates(t,g) ready
                // store x(t+2) from regs (no latency), refill with x(t+3)
                if (stager && t + 2 < TI) {
                    const int row = g * 16 + sgrow;
                    u64 ph, pl; pack_x(xreg[g], ph, pl);
                    const int buf = t & 1;
                    *(u64*)(smem + SM_X + buf * XBUF + (row * XST + seg * 4) * 2)          = ph;
                    *(u64*)(smem + SM_X + buf * XBUF + XPLANE + (row * XST + seg * 4) * 2) = pl;
                    if (t + 3 < TI)
                        xreg[g] = *reinterpret_cast<const float4*>(
                            x + ((size_t)(b0 + row) * TI + (t + 3)) * II + seg * 4);
                }
#pragma unroll
                for (int r = 0; r < 4; ++r) {
                    const int row = g * 16 + rb + r;
                    float ig = sigm_(Gs[u * GST + row]);
                    float fg = sigm_(Gs[(u + 64) * GST + row]);
                    float gg = tanh_(Gs[(u + 128) * GST + row]);
                    float og = sigm_(Gs[(u + 192) * GST + row]);
                    float cv = fmaf(fg, cst[g][r], ig * gg);
                    cst[g][r] = cv;
                    float hv = og * tanh_(cv);
                    uint16_t hh, hl; split_bf16(hv, hh, hl);
                    *(uint16_t*)(smem + SM_H_HI + (row * HST + u) * 2) = hh;
                    *(uint16_t*)(smem + SM_H_LO + (row * HST + u) * 2) = hl;
                    if (t == TI - 1) Hs[row * HH + u] = hv;
                }
                BARR(1 + g);               // h(t,g) ready
            }
        }
    }

    // ---- final linear: out = h_T @ W_out^T + b_out ----
    __syncthreads();
    for (int idx = tid; idx < OUTD * HH; idx += NTHR) Gs[idx] = W_out[idx];
    if (tid < OUTD) Gs[OUTD * HH + tid] = b_out[tid];
    __syncthreads();

    for (int cell = tid; cell < MB * OUTD; cell += NTHR) {
        int row = cell / OUTD;
        int o   = cell - row * OUTD;
        float s = Gs[OUTD * HH + o];
#pragma unroll
        for (int j = 0; j < HH; ++j)
            s = fmaf(Hs[row * HH + j], Gs[o * HH + j], s);
        out[(size_t)(b0 + row) * OUTD + o] = s;
    }
}

extern "C" void kernel_launch(void* const* d_in, const int* in_sizes, int n_in,
                              void* d_out, int out_size)
{
    const float* x     = (const float*)d_in[0];
    const float* W_ih  = (const float*)d_in[1];
    const float* W_hh  = (const float*)d_in[2];
    const float* b_ih  = (const float*)d_in[3];
    const float* b_hh  = (const float*)d_in[4];
    const float* W_out = (const float*)d_in[5];
    const float* b_out = (const float*)d_in[6];
    float* outp = (float*)d_out;

    cudaFuncSetAttribute(lstm_kernel,
                         cudaFuncAttributeMaxDynamicSharedMemorySize, SMEM_BYTES);
    lstm_kernel<<<BB / MB, NTHR, SMEM_BYTES>>>(x, W_ih, W_hh, b_ih, b_hh,
                                               W_out, b_out, outp);
}

// round 10
// speedup vs baseline: 1.3086x; 1.3086x over previous
#include <cuda_runtime.h>
#include <cuda_bf16.h>
#include <stdint.h>

// LSTM_3444563771996 : I=28, H=64, T=128, B=4096, OUT=10
// Homogeneous warps, in-register gate accumulators + activations.
// Warp w owns units [8w,8w+8) x all 16 batch rows; A-tiles pack [i;f],[g;o]
// rows so each thread holds i,f,g,o of the same (unit,batch) cells.
// bf16 hi/lo split mma.sync (3 terms), tanh.approx activations,
// 2 CTAs/SM (MB=16) for cross-CTA pipe overlap.

#define TI   128
#define II   28
#define HH   64
#define GG   256
#define BB   4096
#define OUTD 10
#define MB   16
#define NTHR 256

// strides (elems)
#define WST  72     // whh/h tiles: 144B rows -> conflict-free ldmatrix
#define XSTR 40     // wih/x tiles: 80B rows  -> conflict-free ldmatrix

// ---- SMEM map (bytes). whh staging region is DEAD after init and is
// reused for wih (live) + epilogue scratch. ----
#define SM_WHH_HI 0                    // [256][72] bf16 = 36864
#define SM_WHH_LO 36864                // .. 73728
#define SM_WIH_HI 0                    // overlays dead whh: [256][40] = 20480
#define SM_WIH_LO 20480                // .. 40960
#define SM_SCR    40960                // epilogue scratch (dead region)
#define SM_H_HI   73728                // [16][72] bf16 = 2304
#define SM_H_LO   76032
#define SM_X      78336                // 2 bufs x (hi 1280 + lo 1280)
#define XBUF      2560
#define SMEM_BYTES 83456

typedef unsigned long long u64;

#define LDSM4(r, addr)                                                        \
    asm volatile("ldmatrix.sync.aligned.m8n8.x4.shared.b16 {%0,%1,%2,%3}, [%4];" \
                 : "=r"((r)[0]), "=r"((r)[1]), "=r"((r)[2]), "=r"((r)[3])     \
                 : "r"(addr))

#define MMA16816(d, a, b0_, b1_)                                              \
    asm volatile("mma.sync.aligned.m16n8k16.row.col.f32.bf16.bf16.f32 "       \
                 "{%0,%1,%2,%3}, {%4,%5,%6,%7}, {%8,%9}, {%0,%1,%2,%3};"      \
                 : "+f"((d)[0]), "+f"((d)[1]), "+f"((d)[2]), "+f"((d)[3])     \
                 : "r"((a)[0]), "r"((a)[1]), "r"((a)[2]), "r"((a)[3]),        \
                   "r"(b0_), "r"(b1_))

static __device__ __forceinline__ uint32_t smem_u32(const void* p) {
    uint32_t a;
    asm("{ .reg .u64 t; cvta.to.shared.u64 t, %1; cvt.u32.u64 %0, t; }" : "=r"(a) : "l"(p));
    return a;
}
static __device__ __forceinline__ void split_bf16(float v, uint16_t& hi, uint16_t& lo) {
    __nv_bfloat16 h = __float2bfloat16_rn(v);
    __nv_bfloat16 l = __float2bfloat16_rn(v - __bfloat162float(h));
    hi = __bfloat16_as_ushort(h);
    lo = __bfloat16_as_ushort(l);
}
static __device__ __forceinline__ float tanhap(float v) {
    float r; asm("tanh.approx.f32 %0, %1;" : "=f"(r) : "f"(v)); return r;
}
static __device__ __forceinline__ float sigmap(float v) {
    return fmaf(0.5f, tanhap(0.5f * v), 0.5f);
}
static __device__ __forceinline__ void pack_x(const float4& xv, u64& ph, u64& pl) {
    uint16_t h0,l0,h1,l1,h2,l2,h3,l3;
    split_bf16(xv.x, h0, l0); split_bf16(xv.y, h1, l1);
    split_bf16(xv.z, h2, l2); split_bf16(xv.w, h3, l3);
    ph = (u64)h0 | ((u64)h1 << 16) | ((u64)h2 << 32) | ((u64)h3 << 48);
    pl = (u64)l0 | ((u64)l1 << 16) | ((u64)l2 << 32) | ((u64)l3 << 48);
}

__global__ __launch_bounds__(NTHR, 2)
void lstm_kernel(const float* __restrict__ x,
                 const float* __restrict__ W_ih, const float* __restrict__ W_hh,
                 const float* __restrict__ b_ih, const float* __restrict__ b_hh,
                 const float* __restrict__ W_out, const float* __restrict__ b_out,
                 float* __restrict__ out)
{
    extern __shared__ char smem[];
    const uint32_t sb = smem_u32(smem);
    const int tid  = threadIdx.x;
    const int lane = tid & 31;
    const int warp = tid >> 5;          // 0..7 -> units [8w, 8w+8)
    const int us   = warp * 8;
    const int b0   = blockIdx.x * MB;

    // ---- phase 0: zero h/x tiles; stage W_hh hi/lo [gate][k] ----
    for (int i = tid; i < (SMEM_BYTES - SM_H_HI) / 4; i += NTHR)
        ((uint32_t*)(smem + SM_H_HI))[i] = 0u;
    for (int idx = tid; idx < GG * HH; idx += NTHR) {
        int g = idx >> 6, k = idx & 63;
        uint16_t hi, lo; split_bf16(W_hh[g * HH + k], hi, lo);
        *(uint16_t*)(smem + SM_WHH_HI + (g * WST + k) * 2) = hi;
        *(uint16_t*)(smem + SM_WHH_LO + (g * WST + k) * 2) = lo;
    }
    __syncthreads();

    // ---- lane geometry ----
    const int l7 = lane & 7, lg = lane >> 3;
    const int rIF = ((lg & 1) ? 64 : 0) + us + l7;   // i/f gate rows
    const int rGO = rIF + 128;                       // g/o gate rows
    const uint32_t cof = (uint32_t)((lg >> 1) * 16); // k8 half offset (bytes)
    // B-operand lanes: batch rows
    const int brow = l7 + ((lg >> 1) << 3);
    const uint32_t bko = (uint32_t)((lg & 1) * 16);

    // ---- phase 1: cache all W_hh fragments in registers; stage x(0),x(1) ----
    uint32_t whhIF[4][2][4], whhGO[4][2][4];   // [kc][hi/lo][4]
    {
        const uint32_t aIFh = sb + SM_WHH_HI + (uint32_t)rIF * 144 + cof;
        const uint32_t aIFl = sb + SM_WHH_LO + (uint32_t)rIF * 144 + cof;
        const uint32_t aGOh = sb + SM_WHH_HI + (uint32_t)rGO * 144 + cof;
        const uint32_t aGOl = sb + SM_WHH_LO + (uint32_t)rGO * 144 + cof;
#pragma unroll
        for (int kc = 0; kc < 4; ++kc) {
            LDSM4(whhIF[kc][0], aIFh + kc * 32);
            LDSM4(whhIF[kc][1], aIFl + kc * 32);
            LDSM4(whhGO[kc][0], aGOh + kc * 32);
            LDSM4(whhGO[kc][1], aGOl + kc * 32);
        }
    }
    for (int idx = tid; idx < 2 * MB * 7; idx += NTHR) {
        int ts = idx / (MB * 7), rem = idx % (MB * 7);
        int row = rem / 7, seg = rem % 7;
        const float4 xv = *reinterpret_cast<const float4*>(
            x + ((size_t)(b0 + row) * TI + ts) * II + seg * 4);
        u64 ph, pl; pack_x(xv, ph, pl);
        *(u64*)(smem + SM_X + ts * XBUF + (row * XSTR + seg * 4) * 2)        = ph;
        *(u64*)(smem + SM_X + ts * XBUF + 1280 + (row * XSTR + seg * 4) * 2) = pl;
    }
    __syncthreads();

    // ---- phase 2: zero wih region (overwrites dead whh-hi) ----
    for (int i = tid; i < 40960 / 4; i += NTHR) ((uint32_t*)smem)[i] = 0u;
    __syncthreads();

    // ---- phase 3: stage W_ih hi/lo [gate][k0..27] ----
    for (int idx = tid; idx < GG * II; idx += NTHR) {
        int g = idx / II, k = idx - g * II;
        uint16_t hi, lo; split_bf16(W_ih[g * II + k], hi, lo);
        *(uint16_t*)(smem + SM_WIH_HI + (g * XSTR + k) * 2) = hi;
        *(uint16_t*)(smem + SM_WIH_LO + (g * XSTR + k) * 2) = lo;
    }

    // per-thread cell constants
    const int grow = lane >> 2;           // unit within slice
    const int bcol = (lane & 3) * 2;
    const int u    = us + grow;           // this thread's hidden unit
    const float bI = b_ih[u]       + b_hh[u];
    const float bF = b_ih[u + 64]  + b_hh[u + 64];
    const float bG = b_ih[u + 128] + b_hh[u + 128];
    const float bO = b_ih[u + 192] + b_hh[u + 192];
    float c[4] = {0.f, 0.f, 0.f, 0.f};

    // address bases
    const uint32_t xIFh = sb + SM_WIH_HI + (uint32_t)rIF * 80 + cof;
    const uint32_t xIFl = sb + SM_WIH_LO + (uint32_t)rIF * 80 + cof;
    const uint32_t xGOh = sb + SM_WIH_HI + (uint32_t)rGO * 80 + cof;
    const uint32_t xGOl = sb + SM_WIH_LO + (uint32_t)rGO * 80 + cof;
    const uint32_t bhh = sb + SM_H_HI + (uint32_t)brow * 144 + bko;
    const uint32_t bhl = sb + SM_H_LO + (uint32_t)brow * 144 + bko;
    const uint32_t bxo = (uint32_t)brow * 80 + bko;

    // x prefetch: threads < 112 each own (row, seg)
    const bool stager = tid < MB * 7;
    const int srow = tid / 7, sseg = tid % 7;
    float4 xreg;
    if (stager)
        xreg = *reinterpret_cast<const float4*>(
            x + ((size_t)(b0 + srow) * TI + 2) * II + sseg * 4);

    __syncthreads();

    float accIF[2][4], accGO[2][4];
    // xw(t) into acc (t=0 uses buf0)
    auto xw_compute = [&](int buf) {
#pragma unroll
        for (int j = 0; j < 2; ++j) {
            accIF[j][0] = bI; accIF[j][1] = bI; accIF[j][2] = bF; accIF[j][3] = bF;
            accGO[j][0] = bG; accGO[j][1] = bG; accGO[j][2] = bO; accGO[j][3] = bO;
        }
        const uint32_t xh = sb + SM_X + buf * XBUF + bxo;
        const uint32_t xl = xh + 1280;
#pragma unroll
        for (int kc = 0; kc < 2; ++kc) {
            uint32_t wIFh[4], wIFl[4], wGOh[4], wGOl[4], bh[4], bl[4];
            LDSM4(wIFh, xIFh + kc * 32);
            LDSM4(wIFl, xIFl + kc * 32);
            LDSM4(wGOh, xGOh + kc * 32);
            LDSM4(wGOl, xGOl + kc * 32);
            LDSM4(bh, xh + kc * 32);
            LDSM4(bl, xl + kc * 32);
#pragma unroll
            for (int j = 0; j < 2; ++j) {
                MMA16816(accIF[j], wIFh, bh[2*j], bh[2*j+1]);
                MMA16816(accIF[j], wIFh, bl[2*j], bl[2*j+1]);
                MMA16816(accIF[j], wIFl, bh[2*j], bh[2*j+1]);
                MMA16816(accGO[j], wGOh, bh[2*j], bh[2*j+1]);
                MMA16816(accGO[j], wGOh, bl[2*j], bl[2*j+1]);
                MMA16816(accGO[j], wGOl, bh[2*j], bh[2*j+1]);
            }
        }
    };
    xw_compute(0);

    for (int t = 0; t < TI; ++t) {
        // ---- h-GEMM: acc += W_hh * h(t-1) ----
#pragma unroll
        for (int kc = 0; kc < 4; ++kc) {
            uint32_t bh[4], bl[4];
            LDSM4(bh, bhh + kc * 32);
            LDSM4(bl, bhl + kc * 32);
#pragma unroll
            for (int j = 0; j < 2; ++j) {
                MMA16816(accIF[j], whhIF[kc][0], bh[2*j], bh[2*j+1]);
                MMA16816(accIF[j], whhIF[kc][0], bl[2*j], bl[2*j+1]);
                MMA16816(accIF[j], whhIF[kc][1], bh[2*j], bh[2*j+1]);
                MMA16816(accGO[j], whhGO[kc][0], bh[2*j], bh[2*j+1]);
                MMA16816(accGO[j], whhGO[kc][0], bl[2*j], bl[2*j+1]);
                MMA16816(accGO[j], whhGO[kc][1], bh[2*j], bh[2*j+1]);
            }
        }
        __syncthreads();   // all h(t-1) reads complete

        // ---- in-register activations; h -> SMEM tiles ----
#pragma unroll
        for (int j = 0; j < 2; ++j)
#pragma unroll
            for (int e = 0; e < 2; ++e) {
                float ig = sigmap(accIF[j][e]);
                float fg = sigmap(accIF[j][2 + e]);
                float gg = tanhap(accGO[j][e]);
                float og = sigmap(accGO[j][2 + e]);
                float cv = fmaf(fg, c[j * 2 + e], ig * gg);
                c[j * 2 + e] = cv;
                float hv = og * tanhap(cv);
                uint16_t hh16, hl16; split_bf16(hv, hh16, hl16);
                const int cb = j * 8 + bcol + e;    // batch row
                *(uint16_t*)(smem + SM_H_HI + (cb * WST + u) * 2) = hh16;
                *(uint16_t*)(smem + SM_H_LO + (cb * WST + u) * 2) = hl16;
            }
        // stage x(t+2) from regs; refill with x(t+3)
        if (stager && t + 2 < TI) {
            u64 ph, pl; pack_x(xreg, ph, pl);
            const int buf = t & 1;
            *(u64*)(smem + SM_X + buf * XBUF + (srow * XSTR + sseg * 4) * 2)        = ph;
            *(u64*)(smem + SM_X + buf * XBUF + 1280 + (srow * XSTR + sseg * 4) * 2) = pl;
            if (t + 3 < TI)
                xreg = *reinterpret_cast<const float4*>(
                    x + ((size_t)(b0 + srow) * TI + (t + 3)) * II + sseg * 4);
        }
        __syncthreads();   // h(t) visible to all warps

        if (t + 1 < TI) xw_compute((t + 1) & 1);
    }

    // ---- final linear: out = h_T @ W_out^T + b_out ----
    float* scr = (float*)(smem + SM_SCR);
    for (int idx = tid; idx < OUTD * HH; idx += NTHR) scr[idx] = W_out[idx];
    if (tid < OUTD) scr[OUTD * HH + tid] = b_out[tid];
    __syncthreads();

    const __nv_bfloat16* hhp = (const __nv_bfloat16*)(smem + SM_H_HI);
    const __nv_bfloat16* hlp = (const __nv_bfloat16*)(smem + SM_H_LO);
    for (int cell = tid; cell < MB * OUTD; cell += NTHR) {
        int row = cell / OUTD;
        int o   = cell - row * OUTD;
        float s = scr[OUTD * HH + o];
#pragma unroll
        for (int j = 0; j < HH; ++j) {
            float hv = __bfloat162float(hhp[row * WST + j]) +
                       __bfloat162float(hlp[row * WST + j]);
            s = fmaf(hv, scr[o * HH + j], s);
        }
        out[(size_t)(b0 + row) * OUTD + o] = s;
    }
}

extern "C" void kernel_launch(void* const* d_in, const int* in_sizes, int n_in,
                              void* d_out, int out_size)
{
    const float* x     = (const float*)d_in[0];
    const float* W_ih  = (const float*)d_in[1];
    const float* W_hh  = (const float*)d_in[2];
    const float* b_ih  = (const float*)d_in[3];
    const float* b_hh  = (const float*)d_in[4];
    const float* W_out = (const float*)d_in[5];
    const float* b_out = (const float*)d_in[6];
    float* outp = (float*)d_out;

    cudaFuncSetAttribute(lstm_kernel,
                         cudaFuncAttributeMaxDynamicSharedMemorySize, SMEM_BYTES);
    lstm_kernel<<<BB / MB, NTHR, SMEM_BYTES>>>(x, W_ih, W_hh, b_ih, b_hh,
                                               W_out, b_out, outp);
}